// round 14
// baseline (speedup 1.0000x reference)
#include <cuda_runtime.h>
#include <cuda_bf16.h>
#include <cuda_fp16.h>
#include <cstdint>

// ---------------------------------------------------------------------------
// GraphNetBlock, GB300 round 13 (mma.sync path; tcgen05 blocked by compute_103
// PTX target in the harness toolchain).
//   agg = segment_sum(edge_features, receivers)             (red.v4 atomics)
//   new_nodes = LN( [node_f, agg] @ Wn + bn )
//   P         = new_nodes @ [We_s | We_r]        (50k x 256, per-NODE)
//   new_edges = LN( ef @ We_e + P[s,0:128] + P[r,128:256] + be )
// R13: warp layout 2m x 2n (warp tile 32x64) — halves LDSM (the L1 wall at
//      55%); A prep is now a single cvt so the R7 A-cost penalty is gone.
// GEMMs: mma.sync m16n8k16 f16 single-term (rel_err 3.8e-4 << 1e-3 gate).
// ---------------------------------------------------------------------------

#define NMAX 50000

static __device__ float g_agg[(size_t)NMAX * 128];
static __device__ float g_P[(size_t)NMAX * 256];
static __device__ __half g_nwT[128 * 256];   // node fused W^T, pitch 256
static __device__ __half g_PwT[256 * 128];   // [We_s|We_r]^T, pitch 128
static __device__ __half g_CwT[128 * 128];   // We_e^T, pitch 128
static __device__ float g_nbias[128];
static __device__ float g_ebias[128];

// --------------------------- weight prep -----------------------------------
__global__ void prep_weights_kernel(
    const float* __restrict__ nw1, const float* __restrict__ nb1,
    const float* __restrict__ nw2, const float* __restrict__ nb2,
    const float* __restrict__ ew1, const float* __restrict__ eb1,
    const float* __restrict__ ew2, const float* __restrict__ eb2)
{
    const int b = blockIdx.x;
    const int n = threadIdx.x;  // output column 0..127
    const float* row; const float* w2;
    __half* dh = nullptr;
    float* bd = nullptr;
    float extra = 0.0f;
    int pitch = 0, kk = 0, row_off = 0;
    if (b < 256) {
        row = nw1 + (size_t)b * 128; w2 = nw2;
        dh = g_nwT; pitch = 256; kk = b;
    } else if (b == 256) {
        row = nb1; w2 = nw2; bd = g_nbias; extra = nb2[n];
    } else if (b < 641) {
        int k = b - 257;           // 0..383 into edge W
        row = ew1 + (size_t)k * 128; w2 = ew2;
        if (k < 128)      { dh = g_PwT; pitch = 128; row_off = 0;   kk = k; }
        else if (k < 256) { dh = g_PwT; pitch = 128; row_off = 128; kk = k - 128; }
        else              { dh = g_CwT; pitch = 128; row_off = 0;   kk = k - 256; }
    } else {
        row = eb1; w2 = ew2; bd = g_ebias; extra = eb2[n];
    }
    float s = extra;
    #pragma unroll 4
    for (int j = 0; j < 128; j++)
        s = fmaf(row[j], w2[j * 128 + n], s);
    if (bd) {
        bd[n] = s;
    } else {
        dh[(size_t)(row_off + n) * pitch + kk] = __float2half_rn(s);
    }
}

// --------------------------- agg zero + scatter ----------------------------
__global__ void zero_agg_kernel(int n4)
{
    int i = blockIdx.x * blockDim.x + threadIdx.x;
    if (i < n4)
        reinterpret_cast<float4*>(g_agg)[i] = make_float4(0.f, 0.f, 0.f, 0.f);
}

__global__ void scatter_add_kernel(const float* __restrict__ ef,
                                   const int* __restrict__ recv, int E)
{
    long long t = (long long)blockIdx.x * blockDim.x + threadIdx.x;
    int e = (int)(t >> 5);
    if (e >= E) return;
    int c = (int)(t & 31);
    float4 v = __ldcs(reinterpret_cast<const float4*>(ef) + (size_t)e * 32 + c);
    float* dst = g_agg + (size_t)recv[e] * 128 + c * 4;
    asm volatile("red.global.add.v4.f32 [%0], {%1,%2,%3,%4};"
                 :: "l"(dst), "f"(v.x), "f"(v.y), "f"(v.z), "f"(v.w)
                 : "memory");
}

// --------------------------- mma helpers -----------------------------------
__device__ __forceinline__ void mma16816h(float c[4], const uint32_t a[4],
                                          uint32_t b0, uint32_t b1)
{
    asm volatile(
        "mma.sync.aligned.m16n8k16.row.col.f32.f16.f16.f32 "
        "{%0,%1,%2,%3}, {%4,%5,%6,%7}, {%8,%9}, {%0,%1,%2,%3};"
        : "+f"(c[0]), "+f"(c[1]), "+f"(c[2]), "+f"(c[3])
        : "r"(a[0]), "r"(a[1]), "r"(a[2]), "r"(a[3]), "r"(b0), "r"(b1));
}

__device__ __forceinline__ void ldsm4(uint32_t& r0, uint32_t& r1,
                                      uint32_t& r2, uint32_t& r3,
                                      const __half* p)
{
    uint32_t a = (uint32_t)__cvta_generic_to_shared(p);
    asm volatile("ldmatrix.sync.aligned.m8n8.x4.shared.b16 {%0,%1,%2,%3}, [%4];"
                 : "=r"(r0), "=r"(r1), "=r"(r2), "=r"(r3) : "r"(a));
}

__device__ __forceinline__ uint32_t cvt_h2(float2 v)
{
    __half2 h = __float22half2_rn(v);
    return *reinterpret_cast<uint32_t*>(&h);
}

// --------------------------- fused GEMM kernels ----------------------------
// MODE 0: node pass.  A = [node_f | g_agg], K=256, epi: +nbias, LN -> out.
// MODE 1: P pass.     A = new_nodes, K=128, W col-block = blockIdx.y,
//                     epi: plain store into g_P (pitch 256).
// MODE 2: edge pass.  A = edge_f (streaming), K=128,
//                     epi: + g_P[s,0:128] + g_P[r,128:256] + ebias, LN -> out.
// CTA = 128 threads (4 warps) as 2(m) x 2(n); warp tile = 32 rows x 64 cols.
// Each ldsm.x4 feeds 4 MMAs (2 m-blocks x 2 n8), all-distinct accumulators.
template<int MODE, int NCHUNK>
__global__ __launch_bounds__(128, 4) void mlp_ln_kernel(
    const float* __restrict__ xA,
    const int* __restrict__ senders,
    const int* __restrict__ receivers,
    const float* __restrict__ ln_g,
    const float* __restrict__ ln_b,
    float* __restrict__ out, int M)
{
    __shared__ __half SB[128 * 72];
    __shared__ float s_bias[128], s_g[128], s_b[128];
    __shared__ float2 s_part[2][64];

    const int tid = threadIdx.x;
    const int warp = tid >> 5, lane = tid & 31;
    const int g = lane >> 2, q = lane & 3;
    const int mw = warp & 1;         // m-warp 0..1 (rows mw*32..+31)
    const int nw = warp >> 1;        // n-warp 0..1 (cols nw*64..+63)
    const int laneRow = ((lane >> 4) << 3) + (lane & 7);
    const int laneK = ((lane >> 3) & 1) << 3;

    if (MODE != 1) {
        s_bias[tid] = MODE ? g_ebias[tid] : g_nbias[tid];
        s_g[tid] = ln_g[tid];
        s_b[tid] = ln_b[tid];
    }

    const int rowb = blockIdx.x * 64 + mw * 32 + g;   // this thread's row 0
    int rc[4];
    #pragma unroll
    for (int j = 0; j < 4; j++) rc[j] = min(rowb + j * 8, M - 1);

    const __half* W;
    int wpitch;
    int ncol0 = 0;
    if (MODE == 0) { W = g_nwT; wpitch = 256; }
    else if (MODE == 1) {
        ncol0 = blockIdx.y * 128;
        W = g_PwT + (size_t)ncol0 * 128;
        wpitch = 128;
    } else { W = g_CwT; wpitch = 128; }

    // acc[m*8 + nt2*2 + p] : m in {0,1} (rows +0/+16), 8 n8-tiles of 64 cols
    float acc[16][4];
    #pragma unroll
    for (int i = 0; i < 16; i++) {
        acc[i][0] = 0.f; acc[i][1] = 0.f; acc[i][2] = 0.f; acc[i][3] = 0.f;
    }

    #pragma unroll
    for (int kc = 0; kc < NCHUNK; kc++) {
        __syncthreads();
        #pragma unroll
        for (int i = 0; i < 8; i++) {
            int idx = tid + i * 128;         // 0..1023
            int n = idx >> 3, j = idx & 7;   // smem row, int4-within-row
            reinterpret_cast<int4*>(SB + n * 72)[j] =
                reinterpret_cast<const int4*>(W + (size_t)n * wpitch + kc * 64)[j];
        }
        __syncthreads();

        const float* base = (MODE == 0) ? ((kc < 2) ? xA : g_agg) : xA;
        const int cb = (MODE == 0) ? (kc & 1) * 64 : kc * 64;
        const float* pa0 = base + (size_t)rc[0] * 128 + cb;
        const float* pa1 = base + (size_t)rc[1] * 128 + cb;
        const float* pa2 = base + (size_t)rc[2] * 128 + cb;
        const float* pa3 = base + (size_t)rc[3] * 128 + cb;

        // prefetch A for ks=0: v[0..3] m-block0 (rows g,g+8), v[4..7] m-block1
        float2 v[8];
        {
            const int c0 = q * 2;
            if (MODE == 2) {
                v[0] = __ldcs(reinterpret_cast<const float2*>(pa0 + c0));
                v[1] = __ldcs(reinterpret_cast<const float2*>(pa1 + c0));
                v[2] = __ldcs(reinterpret_cast<const float2*>(pa0 + c0 + 8));
                v[3] = __ldcs(reinterpret_cast<const float2*>(pa1 + c0 + 8));
                v[4] = __ldcs(reinterpret_cast<const float2*>(pa2 + c0));
                v[5] = __ldcs(reinterpret_cast<const float2*>(pa3 + c0));
                v[6] = __ldcs(reinterpret_cast<const float2*>(pa2 + c0 + 8));
                v[7] = __ldcs(reinterpret_cast<const float2*>(pa3 + c0 + 8));
            } else {
                v[0] = *reinterpret_cast<const float2*>(pa0 + c0);
                v[1] = *reinterpret_cast<const float2*>(pa1 + c0);
                v[2] = *reinterpret_cast<const float2*>(pa0 + c0 + 8);
                v[3] = *reinterpret_cast<const float2*>(pa1 + c0 + 8);
                v[4] = *reinterpret_cast<const float2*>(pa2 + c0);
                v[5] = *reinterpret_cast<const float2*>(pa3 + c0);
                v[6] = *reinterpret_cast<const float2*>(pa2 + c0 + 8);
                v[7] = *reinterpret_cast<const float2*>(pa3 + c0 + 8);
            }
        }

        #pragma unroll 1
        for (int ks = 0; ks < 4; ks++) {
            uint32_t a0h[4], a1h[4];
            a0h[0] = cvt_h2(v[0]);
            a0h[1] = cvt_h2(v[1]);
            a0h[2] = cvt_h2(v[2]);
            a0h[3] = cvt_h2(v[3]);
            a1h[0] = cvt_h2(v[4]);
            a1h[1] = cvt_h2(v[5]);
            a1h[2] = cvt_h2(v[6]);
            a1h[3] = cvt_h2(v[7]);

            // prefetch A for ks+1 (overlaps the mma chain below)
            if (ks < 3) {
                const int c1 = (ks + 1) * 16 + q * 2;
                if (MODE == 2) {
                    v[0] = __ldcs(reinterpret_cast<const float2*>(pa0 + c1));
                    v[1] = __ldcs(reinterpret_cast<const float2*>(pa1 + c1));
                    v[2] = __ldcs(reinterpret_cast<const float2*>(pa0 + c1 + 8));
                    v[3] = __ldcs(reinterpret_cast<const float2*>(pa1 + c1 + 8));
                    v[4] = __ldcs(reinterpret_cast<const float2*>(pa2 + c1));
                    v[5] = __ldcs(reinterpret_cast<const float2*>(pa3 + c1));
                    v[6] = __ldcs(reinterpret_cast<const float2*>(pa2 + c1 + 8));
                    v[7] = __ldcs(reinterpret_cast<const float2*>(pa3 + c1 + 8));
                } else {
                    v[0] = *reinterpret_cast<const float2*>(pa0 + c1);
                    v[1] = *reinterpret_cast<const float2*>(pa1 + c1);
                    v[2] = *reinterpret_cast<const float2*>(pa0 + c1 + 8);
                    v[3] = *reinterpret_cast<const float2*>(pa1 + c1 + 8);
                    v[4] = *reinterpret_cast<const float2*>(pa2 + c1);
                    v[5] = *reinterpret_cast<const float2*>(pa3 + c1);
                    v[6] = *reinterpret_cast<const float2*>(pa2 + c1 + 8);
                    v[7] = *reinterpret_cast<const float2*>(pa3 + c1 + 8);
                }
            }

            const int kcol = ks * 16 + laneK;
            // 4 LDSM (warp's 64 cols), then 16 MMAs, all-distinct accs.
            uint32_t bh[4][4];
            #pragma unroll
            for (int j = 0; j < 4; j++) {
                const int srow = nw * 64 + j * 16 + laneRow;
                ldsm4(bh[j][0], bh[j][1], bh[j][2], bh[j][3],
                      SB + srow * 72 + kcol);
            }
            #pragma unroll
            for (int j = 0; j < 4; j++) {
                mma16816h(acc[2 * j],     a0h, bh[j][0], bh[j][1]);
                mma16816h(acc[2 * j + 1], a0h, bh[j][2], bh[j][3]);
            }
            #pragma unroll
            for (int j = 0; j < 4; j++) {
                mma16816h(acc[8 + 2 * j],     a1h, bh[j][0], bh[j][1]);
                mma16816h(acc[8 + 2 * j + 1], a1h, bh[j][2], bh[j][3]);
            }
        }
    }

    // ---------------- epilogues -------------------------------------------
    const int ncb = nw * 64;                 // warp's column base (0 or 64)

    if (MODE == 1) {
        #pragma unroll
        for (int j = 0; j < 4; j++) {
            const int grow = rowb + j * 8;
            if (grow < M) {
                float* o = g_P + (size_t)grow * 256 + ncol0 + ncb;
                const int m = j >> 1, pr = (j & 1) * 2;
                #pragma unroll
                for (int nt = 0; nt < 8; nt++) {
                    *reinterpret_cast<float2*>(o + nt * 8 + q * 2) =
                        make_float2(acc[m * 8 + nt][pr], acc[m * 8 + nt][pr + 1]);
                }
            }
        }
        return;
    }

    // bias (+ P gathers) and per-row partial sums over this warp's 64 cols
    const float* Ps[4];
    const float* Pd[4];
    if (MODE == 2) {
        #pragma unroll
        for (int j = 0; j < 4; j++) {
            Ps[j] = g_P + (size_t)senders[rc[j]] * 256 + ncb;
            Pd[j] = g_P + (size_t)receivers[rc[j]] * 256 + 128 + ncb;
        }
    }
    float S[4] = {0.f, 0.f, 0.f, 0.f};
    float Q[4] = {0.f, 0.f, 0.f, 0.f};
    #pragma unroll
    for (int nt = 0; nt < 8; nt++) {
        const int cc = nt * 8 + q * 2;       // offset within warp's 64 cols
        const float b0 = s_bias[ncb + cc], b1 = s_bias[ncb + cc + 1];
        #pragma unroll
        for (int j = 0; j < 4; j++) {
            const int m = j >> 1, pr = (j & 1) * 2;
            float v0 = acc[m * 8 + nt][pr] + b0;
            float v1 = acc[m * 8 + nt][pr + 1] + b1;
            if (MODE == 2) {
                float2 aa = *reinterpret_cast<const float2*>(Ps[j] + cc);
                float2 bb = *reinterpret_cast<const float2*>(Pd[j] + cc);
                v0 += aa.x + bb.x;
                v1 += aa.y + bb.y;
            }
            acc[m * 8 + nt][pr] = v0;
            acc[m * 8 + nt][pr + 1] = v1;
            S[j] += v0 + v1;
            Q[j] += v0 * v0 + v1 * v1;
        }
    }
    #pragma unroll
    for (int msk = 1; msk <= 2; msk <<= 1) {
        #pragma unroll
        for (int j = 0; j < 4; j++) {
            S[j] += __shfl_xor_sync(0xffffffffu, S[j], msk);
            Q[j] += __shfl_xor_sync(0xffffffffu, Q[j], msk);
        }
    }
    // cross-warp (n-split) combine via SMEM
    if (q == 0) {
        #pragma unroll
        for (int j = 0; j < 4; j++)
            s_part[nw][mw * 32 + g + j * 8] = make_float2(S[j], Q[j]);
    }
    __syncthreads();
    #pragma unroll
    for (int j = 0; j < 4; j++) {
        float2 o = s_part[nw ^ 1][mw * 32 + g + j * 8];
        S[j] += o.x;
        Q[j] += o.y;
    }

    const float inv = 1.0f / 128.0f;
    #pragma unroll
    for (int j = 0; j < 4; j++) {
        const int grow = rowb + j * 8;
        const float mu = S[j] * inv;
        const float rs = rsqrtf(fmaxf(Q[j] * inv - mu * mu, 0.f) + 1e-5f);
        if (grow < M) {
            float* o = out + (size_t)grow * 128 + ncb;
            const int m = j >> 1, pr = (j & 1) * 2;
            #pragma unroll
            for (int nt = 0; nt < 8; nt++) {
                const int cc = nt * 8 + q * 2;
                float2 w;
                w.x = (acc[m * 8 + nt][pr] - mu) * rs * s_g[ncb + cc] + s_b[ncb + cc];
                w.y = (acc[m * 8 + nt][pr + 1] - mu) * rs * s_g[ncb + cc + 1] + s_b[ncb + cc + 1];
                *reinterpret_cast<float2*>(o + cc) = w;
            }
        }
    }
}

// ---------------------------------------------------------------------------
extern "C" void kernel_launch(void* const* d_in, const int* in_sizes, int n_in,
                              void* d_out, int out_size)
{
    const float* node_f   = (const float*)d_in[0];
    const float* edge_f   = (const float*)d_in[1];
    const int*   senders  = (const int*)d_in[2];
    const int*   receivers= (const int*)d_in[3];
    const float* nw1 = (const float*)d_in[4];
    const float* nb1 = (const float*)d_in[5];
    const float* nw2 = (const float*)d_in[6];
    const float* nb2 = (const float*)d_in[7];
    const float* nlg = (const float*)d_in[8];
    const float* nlb = (const float*)d_in[9];
    const float* ew1 = (const float*)d_in[10];
    const float* eb1 = (const float*)d_in[11];
    const float* ew2 = (const float*)d_in[12];
    const float* eb2 = (const float*)d_in[13];
    const float* elg = (const float*)d_in[14];
    const float* elb = (const float*)d_in[15];

    const int N = in_sizes[0] / 128;   // 50000
    const int E = in_sizes[2];         // 300000

    float* out_nodes = (float*)d_out;
    float* out_edges = out_nodes + (size_t)N * 128;

    // 1) fuse W1@W2 (+ bias), transpose, convert to fp16
    prep_weights_kernel<<<642, 128>>>(nw1, nb1, nw2, nb2, ew1, eb1, ew2, eb2);

    // 2) agg = segment_sum(edge_features, receivers)
    zero_agg_kernel<<<(N * 32 + 255) / 256, 256>>>(N * 32);
    {
        long long threads = (long long)E * 32;
        int grid = (int)((threads + 255) / 256);
        scatter_add_kernel<<<grid, 256>>>(edge_f, receivers, E);
    }

    // 3) node pass: LN([node_f, agg] @ Wn + bn) -> out_nodes
    mlp_ln_kernel<0, 4><<<(N + 63) / 64, 128>>>(
        node_f, nullptr, nullptr, nlg, nlb, out_nodes, N);

    // 4) P pass: P = new_nodes @ [We_s|We_r] -> g_P (50k x 256)
    {
        dim3 grid((N + 63) / 64, 2);
        mlp_ln_kernel<1, 2><<<grid, 128>>>(
            out_nodes, nullptr, nullptr, nullptr, nullptr, nullptr, N);
    }

    // 5) edge pass: LN(ef @ We_e + P[s,0:128] + P[r,128:256] + be) -> out_edges
    mlp_ln_kernel<2, 2><<<(E + 63) / 64, 128>>>(
        edge_f, senders, receivers, elg, elb, out_edges, E);
}

// round 15
// speedup vs baseline: 1.0788x; 1.0788x over previous
#include <cuda_runtime.h>
#include <cuda_bf16.h>
#include <cuda_fp16.h>
#include <cstdint>

// ---------------------------------------------------------------------------
// GraphNetBlock, GB300 round 14 (mma.sync path; tcgen05 blocked by compute_103
// PTX target in the harness toolchain).
//   agg = segment_sum(edge_features, receivers)             (red.v4 atomics)
//   new_nodes = LN( [node_f, agg] @ Wn + bn )
//   P         = new_nodes @ [We_s | We_r]        (50k x 256, per-NODE)
//   new_edges = LN( ef @ We_e + P[s,0:128] + P[r,128:256] + be )
// R14: full 128-K B panel staged once per segment (pitch-136 SMEM), mainloop
//      runs 8 k-steps with ZERO barriers (R12 was barrier-bound: issue 15%).
//      MODE0 K=256 handled as node_f@Wn_top + agg@Wn_bot (2 segments).
// GEMMs: mma.sync m16n8k16 f16 single-term (rel_err 3.8e-4 << 1e-3 gate),
//        R12 16x128 warp tile (L1 = LDG+LDS; reshapes proven losers twice).
// ---------------------------------------------------------------------------

#define NMAX 50000

static __device__ float g_agg[(size_t)NMAX * 128];
static __device__ float g_P[(size_t)NMAX * 256];
static __device__ __half g_nwT[128 * 256];   // node fused W^T, pitch 256
static __device__ __half g_PwT[256 * 128];   // [We_s|We_r]^T, pitch 128
static __device__ __half g_CwT[128 * 128];   // We_e^T, pitch 128
static __device__ float g_nbias[128];
static __device__ float g_ebias[128];

// --------------------------- weight prep -----------------------------------
__global__ void prep_weights_kernel(
    const float* __restrict__ nw1, const float* __restrict__ nb1,
    const float* __restrict__ nw2, const float* __restrict__ nb2,
    const float* __restrict__ ew1, const float* __restrict__ eb1,
    const float* __restrict__ ew2, const float* __restrict__ eb2)
{
    const int b = blockIdx.x;
    const int n = threadIdx.x;  // output column 0..127
    const float* row; const float* w2;
    __half* dh = nullptr;
    float* bd = nullptr;
    float extra = 0.0f;
    int pitch = 0, kk = 0, row_off = 0;
    if (b < 256) {
        row = nw1 + (size_t)b * 128; w2 = nw2;
        dh = g_nwT; pitch = 256; kk = b;
    } else if (b == 256) {
        row = nb1; w2 = nw2; bd = g_nbias; extra = nb2[n];
    } else if (b < 641) {
        int k = b - 257;           // 0..383 into edge W
        row = ew1 + (size_t)k * 128; w2 = ew2;
        if (k < 128)      { dh = g_PwT; pitch = 128; row_off = 0;   kk = k; }
        else if (k < 256) { dh = g_PwT; pitch = 128; row_off = 128; kk = k - 128; }
        else              { dh = g_CwT; pitch = 128; row_off = 0;   kk = k - 256; }
    } else {
        row = eb1; w2 = ew2; bd = g_ebias; extra = eb2[n];
    }
    float s = extra;
    #pragma unroll 4
    for (int j = 0; j < 128; j++)
        s = fmaf(row[j], w2[j * 128 + n], s);
    if (bd) {
        bd[n] = s;
    } else {
        dh[(size_t)(row_off + n) * pitch + kk] = __float2half_rn(s);
    }
}

// --------------------------- agg zero + scatter ----------------------------
__global__ void zero_agg_kernel(int n4)
{
    int i = blockIdx.x * blockDim.x + threadIdx.x;
    if (i < n4)
        reinterpret_cast<float4*>(g_agg)[i] = make_float4(0.f, 0.f, 0.f, 0.f);
}

__global__ void scatter_add_kernel(const float* __restrict__ ef,
                                   const int* __restrict__ recv, int E)
{
    long long t = (long long)blockIdx.x * blockDim.x + threadIdx.x;
    int e = (int)(t >> 5);
    if (e >= E) return;
    int c = (int)(t & 31);
    float4 v = __ldcs(reinterpret_cast<const float4*>(ef) + (size_t)e * 32 + c);
    float* dst = g_agg + (size_t)recv[e] * 128 + c * 4;
    asm volatile("red.global.add.v4.f32 [%0], {%1,%2,%3,%4};"
                 :: "l"(dst), "f"(v.x), "f"(v.y), "f"(v.z), "f"(v.w)
                 : "memory");
}

// --------------------------- mma helpers -----------------------------------
__device__ __forceinline__ void mma16816h(float c[4], const uint32_t a[4],
                                          uint32_t b0, uint32_t b1)
{
    asm volatile(
        "mma.sync.aligned.m16n8k16.row.col.f32.f16.f16.f32 "
        "{%0,%1,%2,%3}, {%4,%5,%6,%7}, {%8,%9}, {%0,%1,%2,%3};"
        : "+f"(c[0]), "+f"(c[1]), "+f"(c[2]), "+f"(c[3])
        : "r"(a[0]), "r"(a[1]), "r"(a[2]), "r"(a[3]), "r"(b0), "r"(b1));
}

__device__ __forceinline__ void ldsm4(uint32_t& r0, uint32_t& r1,
                                      uint32_t& r2, uint32_t& r3,
                                      const __half* p)
{
    uint32_t a = (uint32_t)__cvta_generic_to_shared(p);
    asm volatile("ldmatrix.sync.aligned.m8n8.x4.shared.b16 {%0,%1,%2,%3}, [%4];"
                 : "=r"(r0), "=r"(r1), "=r"(r2), "=r"(r3) : "r"(a));
}

__device__ __forceinline__ uint32_t cvt_h2(float2 v)
{
    __half2 h = __float22half2_rn(v);
    return *reinterpret_cast<uint32_t*>(&h);
}

#define BPITCH 136   // halves per SMEM B row; 272B stride = 4 banks mod 32

// --------------------------- fused GEMM kernels ----------------------------
// MODE 0: node pass, NSEG=2. seg0: A=node_f, B=Wn[:,0:128];
//                            seg1: A=g_agg,  B=Wn[:,128:256]. +nbias, LN.
// MODE 1: P pass, NSEG=1.    A=new_nodes, B=PwT col-block (blockIdx.y).
// MODE 2: edge pass, NSEG=1. A=edge_f, B=CwT; epi + P gathers + ebias, LN.
// CTA = 128 threads (4 warps), tile 64 rows x 128 cols; warp w rows w*16..+15.
// Per segment: stage full 128-K B panel once, then 8 barrier-free k-steps.
template<int MODE, int NSEG>
__global__ __launch_bounds__(128, 4) void mlp_ln_kernel(
    const float* __restrict__ xA,
    const int* __restrict__ senders,
    const int* __restrict__ receivers,
    const float* __restrict__ ln_g,
    const float* __restrict__ ln_b,
    float* __restrict__ out, int M)
{
    __shared__ __half SB[128 * BPITCH];
    __shared__ float s_bias[128], s_g[128], s_b[128];

    const int tid = threadIdx.x;
    const int warp = tid >> 5, lane = tid & 31;
    const int g = lane >> 2, q = lane & 3;
    const int laneRow = ((lane >> 4) << 3) + (lane & 7);
    const int laneK = ((lane >> 3) & 1) << 3;

    if (MODE != 1) {
        s_bias[tid] = MODE ? g_ebias[tid] : g_nbias[tid];
        s_g[tid] = ln_g[tid];
        s_b[tid] = ln_b[tid];
    }

    const int row0 = blockIdx.x * 64 + warp * 16 + g;
    const int row1 = row0 + 8;
    const int r0c = min(row0, M - 1);
    const int r1c = min(row1, M - 1);

    const __half* W;
    int wpitch;
    int ncol0 = 0;
    if (MODE == 0) { W = g_nwT; wpitch = 256; }
    else if (MODE == 1) {
        ncol0 = blockIdx.y * 128;
        W = g_PwT + (size_t)ncol0 * 128;
        wpitch = 128;
    } else { W = g_CwT; wpitch = 128; }

    // staging geometry: thread handles row n = tid>>4 (+8 per iter), int4 j
    const int st_n = tid >> 4;
    const int st_j = tid & 15;

    float acc[16][4];
    #pragma unroll
    for (int i = 0; i < 16; i++) {
        acc[i][0] = 0.f; acc[i][1] = 0.f; acc[i][2] = 0.f; acc[i][3] = 0.f;
    }

    #pragma unroll
    for (int seg = 0; seg < NSEG; seg++) {
        // ---- stage full 128-K B panel for this segment ----
        if (seg > 0) __syncthreads();        // prior segment's reads done
        #pragma unroll
        for (int i = 0; i < 16; i++) {
            const int n = st_n + i * 8;
            reinterpret_cast<int4*>(SB + n * BPITCH)[st_j] =
                *reinterpret_cast<const int4*>(
                    W + (size_t)n * wpitch + seg * 128 + st_j * 8);
        }
        __syncthreads();

        const float* base = (MODE == 0) ? ((seg == 0) ? xA : g_agg) : xA;
        const float* pa = base + (size_t)r0c * 128;
        const float* pb = base + (size_t)r1c * 128;

        // prefetch A for ks=0
        float2 x00, x10, x01, x11;
        {
            const int c0 = q * 2;
            if (MODE == 2) {
                x00 = __ldcs(reinterpret_cast<const float2*>(pa + c0));
                x10 = __ldcs(reinterpret_cast<const float2*>(pb + c0));
                x01 = __ldcs(reinterpret_cast<const float2*>(pa + c0 + 8));
                x11 = __ldcs(reinterpret_cast<const float2*>(pb + c0 + 8));
            } else {
                x00 = *reinterpret_cast<const float2*>(pa + c0);
                x10 = *reinterpret_cast<const float2*>(pb + c0);
                x01 = *reinterpret_cast<const float2*>(pa + c0 + 8);
                x11 = *reinterpret_cast<const float2*>(pb + c0 + 8);
            }
        }

        // ---- 8 barrier-free k-steps ----
        #pragma unroll 1
        for (int ks = 0; ks < 8; ks++) {
            uint32_t ah[4];
            ah[0] = cvt_h2(x00);
            ah[1] = cvt_h2(x10);
            ah[2] = cvt_h2(x01);
            ah[3] = cvt_h2(x11);

            // prefetch A for ks+1 (overlaps the mma chain below)
            if (ks < 7) {
                const int c1 = (ks + 1) * 16 + q * 2;
                if (MODE == 2) {
                    x00 = __ldcs(reinterpret_cast<const float2*>(pa + c1));
                    x10 = __ldcs(reinterpret_cast<const float2*>(pb + c1));
                    x01 = __ldcs(reinterpret_cast<const float2*>(pa + c1 + 8));
                    x11 = __ldcs(reinterpret_cast<const float2*>(pb + c1 + 8));
                } else {
                    x00 = *reinterpret_cast<const float2*>(pa + c1);
                    x10 = *reinterpret_cast<const float2*>(pb + c1);
                    x01 = *reinterpret_cast<const float2*>(pa + c1 + 8);
                    x11 = *reinterpret_cast<const float2*>(pb + c1 + 8);
                }
            }

            const int kcol = ks * 16 + laneK;
            // Groups of 4 n-tiles: 4 LDSM then 8 independent-acc MMAs.
            #pragma unroll
            for (int grp = 0; grp < 2; grp++) {
                uint32_t bh[4][4];
                #pragma unroll
                for (int j = 0; j < 4; j++) {
                    const int srow = (grp * 4 + j) * 16 + laneRow;
                    ldsm4(bh[j][0], bh[j][1], bh[j][2], bh[j][3],
                          SB + srow * BPITCH + kcol);
                }
                #pragma unroll
                for (int j = 0; j < 4; j++) {
                    mma16816h(acc[2 * (grp * 4 + j)],     ah, bh[j][0], bh[j][1]);
                    mma16816h(acc[2 * (grp * 4 + j) + 1], ah, bh[j][2], bh[j][3]);
                }
            }
        }
    }

    // ---------------- epilogues -------------------------------------------
    if (MODE == 1) {
        if (row0 < M) {
            float* o = g_P + (size_t)row0 * 256 + ncol0;
            #pragma unroll
            for (int nt = 0; nt < 16; nt++) {
                const int c = nt * 8 + q * 2;
                *reinterpret_cast<float2*>(o + c) = make_float2(acc[nt][0], acc[nt][1]);
            }
        }
        if (row1 < M) {
            float* o = g_P + (size_t)row1 * 256 + ncol0;
            #pragma unroll
            for (int nt = 0; nt < 16; nt++) {
                const int c = nt * 8 + q * 2;
                *reinterpret_cast<float2*>(o + c) = make_float2(acc[nt][2], acc[nt][3]);
            }
        }
        return;
    }

    if (MODE == 2) {
        const int s0 = senders[r0c], s1 = senders[r1c];
        const int d0 = receivers[r0c], d1 = receivers[r1c];
        const float* Ps0 = g_P + (size_t)s0 * 256;
        const float* Ps1 = g_P + (size_t)s1 * 256;
        const float* Pd0 = g_P + (size_t)d0 * 256 + 128;
        const float* Pd1 = g_P + (size_t)d1 * 256 + 128;
        #pragma unroll
        for (int nt = 0; nt < 16; nt++) {
            const int c = nt * 8 + q * 2;
            float2 a0 = *reinterpret_cast<const float2*>(Ps0 + c);
            float2 b0 = *reinterpret_cast<const float2*>(Pd0 + c);
            float2 a1 = *reinterpret_cast<const float2*>(Ps1 + c);
            float2 b1 = *reinterpret_cast<const float2*>(Pd1 + c);
            acc[nt][0] += a0.x + b0.x;
            acc[nt][1] += a0.y + b0.y;
            acc[nt][2] += a1.x + b1.x;
            acc[nt][3] += a1.y + b1.y;
        }
    }

    // bias + layernorm + store (MODE 0 and 2)
    float sum0 = 0.f, sq0 = 0.f, sum1 = 0.f, sq1 = 0.f;
    #pragma unroll
    for (int nt = 0; nt < 16; nt++) {
        const int c = nt * 8 + q * 2;
        const float b0 = s_bias[c], b1 = s_bias[c + 1];
        float v0 = acc[nt][0] + b0, v1 = acc[nt][1] + b1;
        float v2 = acc[nt][2] + b0, v3 = acc[nt][3] + b1;
        acc[nt][0] = v0; acc[nt][1] = v1; acc[nt][2] = v2; acc[nt][3] = v3;
        sum0 += v0 + v1; sq0 += v0 * v0 + v1 * v1;
        sum1 += v2 + v3; sq1 += v2 * v2 + v3 * v3;
    }
    #pragma unroll
    for (int m = 1; m <= 2; m <<= 1) {
        sum0 += __shfl_xor_sync(0xffffffffu, sum0, m);
        sq0  += __shfl_xor_sync(0xffffffffu, sq0, m);
        sum1 += __shfl_xor_sync(0xffffffffu, sum1, m);
        sq1  += __shfl_xor_sync(0xffffffffu, sq1, m);
    }
    const float inv = 1.0f / 128.0f;
    const float mu0 = sum0 * inv, mu1 = sum1 * inv;
    const float rs0 = rsqrtf(fmaxf(sq0 * inv - mu0 * mu0, 0.f) + 1e-5f);
    const float rs1 = rsqrtf(fmaxf(sq1 * inv - mu1 * mu1, 0.f) + 1e-5f);

    if (row0 < M) {
        float* o = out + (size_t)row0 * 128;
        #pragma unroll
        for (int nt = 0; nt < 16; nt++) {
            const int c = nt * 8 + q * 2;
            float2 w;
            w.x = (acc[nt][0] - mu0) * rs0 * s_g[c] + s_b[c];
            w.y = (acc[nt][1] - mu0) * rs0 * s_g[c + 1] + s_b[c + 1];
            *reinterpret_cast<float2*>(o + c) = w;
        }
    }
    if (row1 < M) {
        float* o = out + (size_t)row1 * 128;
        #pragma unroll
        for (int nt = 0; nt < 16; nt++) {
            const int c = nt * 8 + q * 2;
            float2 w;
            w.x = (acc[nt][2] - mu1) * rs1 * s_g[c] + s_b[c];
            w.y = (acc[nt][3] - mu1) * rs1 * s_g[c + 1] + s_b[c + 1];
            *reinterpret_cast<float2*>(o + c) = w;
        }
    }
}

// ---------------------------------------------------------------------------
extern "C" void kernel_launch(void* const* d_in, const int* in_sizes, int n_in,
                              void* d_out, int out_size)
{
    const float* node_f   = (const float*)d_in[0];
    const float* edge_f   = (const float*)d_in[1];
    const int*   senders  = (const int*)d_in[2];
    const int*   receivers= (const int*)d_in[3];
    const float* nw1 = (const float*)d_in[4];
    const float* nb1 = (const float*)d_in[5];
    const float* nw2 = (const float*)d_in[6];
    const float* nb2 = (const float*)d_in[7];
    const float* nlg = (const float*)d_in[8];
    const float* nlb = (const float*)d_in[9];
    const float* ew1 = (const float*)d_in[10];
    const float* eb1 = (const float*)d_in[11];
    const float* ew2 = (const float*)d_in[12];
    const float* eb2 = (const float*)d_in[13];
    const float* elg = (const float*)d_in[14];
    const float* elb = (const float*)d_in[15];

    const int N = in_sizes[0] / 128;   // 50000
    const int E = in_sizes[2];         // 300000

    float* out_nodes = (float*)d_out;
    float* out_edges = out_nodes + (size_t)N * 128;

    // 1) fuse W1@W2 (+ bias), transpose, convert to fp16
    prep_weights_kernel<<<642, 128>>>(nw1, nb1, nw2, nb2, ew1, eb1, ew2, eb2);

    // 2) agg = segment_sum(edge_features, receivers)
    zero_agg_kernel<<<(N * 32 + 255) / 256, 256>>>(N * 32);
    {
        long long threads = (long long)E * 32;
        int grid = (int)((threads + 255) / 256);
        scatter_add_kernel<<<grid, 256>>>(edge_f, receivers, E);
    }

    // 3) node pass: LN(node_f@Wn_top + agg@Wn_bot + bn) -> out_nodes
    mlp_ln_kernel<0, 2><<<(N + 63) / 64, 128>>>(
        node_f, nullptr, nullptr, nlg, nlb, out_nodes, N);

    // 4) P pass: P = new_nodes @ [We_s|We_r] -> g_P (50k x 256)
    {
        dim3 grid((N + 63) / 64, 2);
        mlp_ln_kernel<1, 1><<<grid, 128>>>(
            out_nodes, nullptr, nullptr, nullptr, nullptr, nullptr, N);
    }

    // 5) edge pass: LN(ef @ We_e + P[s,0:128] + P[r,128:256] + be) -> out_edges
    mlp_ln_kernel<2, 1><<<(E + 63) / 64, 128>>>(
        edge_f, senders, receivers, elg, elb, out_edges, E);
}